// round 9
// baseline (speedup 1.0000x reference)
#include <cuda_runtime.h>
#include <cstdint>

#define N_NODES 100000
#define N_EDGES 1600000
#define N_PRED  500000
#define D       64
#define NB_SCAN 391   // ceil(N_NODES/256)

// ---------------- device scratch (alloc-free rule: static globals) ----------
__device__ int   g_deg_out[N_NODES];
__device__ int   g_deg_in [N_NODES];
__device__ float g_norm_out[N_NODES];
__device__ float g_norm_in [N_NODES];
__device__ int   g_rowstart[N_NODES];
__device__ int   g_cursor  [N_NODES];
__device__ int   g_blocksum[NB_SCAN];
__device__ int   g_blockoff[NB_SCAN];
__device__ int   g_csr_src [N_EDGES];
__device__ __align__(16) float g_xn [(size_t)N_NODES * D]; // layer-2 input (pre-scaled)
__device__ __align__(16) float g_h  [(size_t)N_NODES * D]; // layer-2 output h
__device__ __align__(16) float g_p  [(size_t)N_NODES * 16];// [pA | pB] per node

// ---------------- degree --------------------------------------------------

__global__ void k_zero_deg() {
    int i = blockIdx.x * blockDim.x + threadIdx.x;
    if (i < N_NODES) { g_deg_out[i] = 0; g_deg_in[i] = 0; }
}

__global__ void k_degree(const int* __restrict__ src, const int* __restrict__ dst) {
    int e = blockIdx.x * blockDim.x + threadIdx.x;
    if (e < N_EDGES) {
        atomicAdd(&g_deg_out[__ldg(&src[e])], 1);
        atomicAdd(&g_deg_in [__ldg(&dst[e])], 1);
    }
}

// ---------------- two-kernel exclusive scan of deg_in -> rowstart -----------
// (proven in rounds 2/4/5/6; the single-pass ticket variant is the prime
//  suspect for the R7/R8 container deaths and has been reverted)

__global__ void k_scan1() {
    __shared__ int sh[256];
    int i = blockIdx.x * 256 + threadIdx.x;
    int v = (i < N_NODES) ? g_deg_in[i] : 0;
    sh[threadIdx.x] = v;
    __syncthreads();
#pragma unroll
    for (int off = 1; off < 256; off <<= 1) {
        int t = (threadIdx.x >= off) ? sh[threadIdx.x - off] : 0;
        __syncthreads();
        sh[threadIdx.x] += t;
        __syncthreads();
    }
    if (i < N_NODES) g_rowstart[i] = sh[threadIdx.x] - v;   // exclusive
    if (threadIdx.x == 255) g_blocksum[blockIdx.x] = sh[255];
}

__global__ void k_scan2() {   // single block of 512, scans NB_SCAN block sums
    __shared__ int sh[512];
    int v = (threadIdx.x < NB_SCAN) ? g_blocksum[threadIdx.x] : 0;
    sh[threadIdx.x] = v;
    __syncthreads();
#pragma unroll
    for (int off = 1; off < 512; off <<= 1) {
        int t = (threadIdx.x >= off) ? sh[threadIdx.x - off] : 0;
        __syncthreads();
        sh[threadIdx.x] += t;
        __syncthreads();
    }
    if (threadIdx.x < NB_SCAN) g_blockoff[threadIdx.x] = sh[threadIdx.x] - v;  // exclusive
}

// finalize rowstart/cursor AND compute norms (fused; both over N_NODES)
__global__ void k_scan3_norms() {
    int i = blockIdx.x * blockDim.x + threadIdx.x;
    if (i < N_NODES) {
        int rs = g_rowstart[i] + g_blockoff[i >> 8];
        g_rowstart[i] = rs;
        g_cursor[i] = rs;
        int dou = g_deg_out[i];
        int din = g_deg_in[i];
        g_norm_out[i] = dou > 0 ? rsqrtf((float)dou) : 0.f;
        g_norm_in [i] = din > 0 ? rsqrtf((float)din) : 0.f;
    }
}

// ---------------- CSR bucket fill -------------------------------------------

__global__ void k_bucket(const int* __restrict__ src, const int* __restrict__ dst) {
    int e = blockIdx.x * blockDim.x + threadIdx.x;
    if (e < N_EDGES) {
        int d = __ldg(&dst[e]);
        int pos = atomicAdd(&g_cursor[d], 1);
        g_csr_src[pos] = __ldg(&src[e]);
    }
}

// ---------------- fused aggregate + GEMM ------------------------------------
// Block = 256 threads = 8 warps = 8 nodes (N_NODES = 8 * 12500 exactly).
// Phase A: warp w pull-aggregates node blockIdx*8+w into smem row
//          (float2 per lane; norm_out[src] applied inline for MODE 0;
//           norm_in applied at the end).
// Phase B: column-per-thread GEMM, W in 64 registers, rows broadcast from
//          smem. MODE 0: relu*norm_out -> g_xn. MODE 1: plain -> g_h.
template <int MODE>
__global__ void __launch_bounds__(256, 2)
k_agg_gemm(const float* __restrict__ xin,
           const float* __restrict__ W, const float* __restrict__ b) {
    const int t    = threadIdx.x;
    const int w    = t >> 5;
    const int lane = t & 31;
    const int node = blockIdx.x * 8 + w;

    const float* in = (MODE == 0) ? xin : (const float*)g_xn;

    __shared__ __align__(16) float rows[8][D];

    // ---- Phase A: aggregation (warp per node) ----
    {
        int start = g_rowstart[node];
        int deg   = g_deg_in[node];
        float2 acc = make_float2(0.f, 0.f);

        for (int base = 0; base < deg; base += 32) {
            int my = base + lane;
            int s_my = (my < deg) ? __ldg(&g_csr_src[start + my]) : 0;
            int cnt = min(32, deg - base);
#pragma unroll 4
            for (int k = 0; k < cnt; k++) {
                int s = __shfl_sync(0xffffffffu, s_my, k);
                float2 v = ((const float2*)(in + (size_t)s * D))[lane];
                if (MODE == 0) {
                    float no = __ldg(&g_norm_out[s]);
                    v.x *= no; v.y *= no;
                }
                acc.x += v.x; acc.y += v.y;
            }
        }
        float ni = g_norm_in[node];
        acc.x *= ni; acc.y *= ni;
        ((float2*)rows[w])[lane] = acc;
    }
    __syncthreads();

    // ---- Phase B: GEMM (column-per-thread, 8 rows in 2 passes) ----
    const int c = t & 63;     // output column
    const int r = t >> 6;     // row slot within pass (0..3)

    float wreg[D];
#pragma unroll
    for (int kk = 0; kk < D; kk++) wreg[kk] = __ldg(&W[kk * D + c]);
    const float bc = __ldg(&b[c]);

#pragma unroll
    for (int rr = 0; rr < 2; rr++) {
        int slot = rr * 4 + r;
        int onode = blockIdx.x * 8 + slot;
        float acc = bc;
        const float4* vrow = (const float4*)rows[slot];
#pragma unroll
        for (int q = 0; q < D / 4; q++) {
            float4 vv = vrow[q];          // broadcast within warp (same slot)
            acc = fmaf(vv.x, wreg[4 * q + 0], acc);
            acc = fmaf(vv.y, wreg[4 * q + 1], acc);
            acc = fmaf(vv.z, wreg[4 * q + 2], acc);
            acc = fmaf(vv.w, wreg[4 * q + 3], acc);
        }
        size_t off = (size_t)onode * D + c;
        if (MODE == 0) {
            acc = fmaxf(acc, 0.f) * g_norm_out[onode];
            g_xn[off] = acc;
        } else {
            g_h[off] = acc;
        }
    }
}

// ---------------- predictor --------------------------------------------------
// Per-node projection: g_p[n][0:8] = h[n] @ Wp[0:64], g_p[n][8:16] = h[n] @ Wp[64:128]
__global__ void __launch_bounds__(256, 2)
k_project(const float* __restrict__ Wp) {
    const int t = threadIdx.x;
    const int c  = t & 15;
    const int nl = t >> 4;

    const int rowoff = (c < 8) ? 0 : 64;
    const int cc = c & 7;
    float w[D];
#pragma unroll
    for (int kk = 0; kk < D; kk++) w[kk] = __ldg(&Wp[(rowoff + kk) * 8 + cc]);

    __shared__ __align__(16) float hs[16 * D];

    for (int base = blockIdx.x * 16; base < N_NODES; base += gridDim.x * 16) {
        if (base + (t >> 4) < N_NODES)
            ((float4*)hs)[t] = ((const float4*)(g_h + (size_t)base * D))[t];
        __syncthreads();

        int node = base + nl;
        if (node < N_NODES) {
            float acc = 0.f;
            const float4* vrow = (const float4*)(hs + nl * D);
#pragma unroll
            for (int q = 0; q < D / 4; q++) {
                float4 vv = vrow[q];
                acc = fmaf(vv.x, w[4 * q + 0], acc);
                acc = fmaf(vv.y, w[4 * q + 1], acc);
                acc = fmaf(vv.z, w[4 * q + 2], acc);
                acc = fmaf(vv.w, w[4 * q + 3], acc);
            }
            g_p[(size_t)node * 16 + c] = acc;
        }
        __syncthreads();
    }
}

__global__ void k_edge_pred(const int* __restrict__ psrc, const int* __restrict__ pdst,
                            const float* __restrict__ bp, float* __restrict__ out) {
    int e = blockIdx.x * blockDim.x + threadIdx.x;
    if (e >= N_PRED) return;
    int u = __ldg(&psrc[e]);
    int v = __ldg(&pdst[e]);
    const float4* pa = (const float4*)(g_p + (size_t)u * 16);
    const float4* pb = (const float4*)(g_p + (size_t)v * 16 + 8);
    float4 a0 = pa[0], a1 = pa[1];
    float4 c0 = pb[0], c1 = pb[1];
    float4 bp0 = ((const float4*)bp)[0];
    float4 bp1 = ((const float4*)bp)[1];
    float4 o0 = make_float4(a0.x + c0.x + bp0.x, a0.y + c0.y + bp0.y,
                            a0.z + c0.z + bp0.z, a0.w + c0.w + bp0.w);
    float4 o1 = make_float4(a1.x + c1.x + bp1.x, a1.y + c1.y + bp1.y,
                            a1.z + c1.z + bp1.z, a1.w + c1.w + bp1.w);
    ((float4*)out)[(size_t)e * 2 + 0] = o0;
    ((float4*)out)[(size_t)e * 2 + 1] = o1;
}

// ---------------- launch ----------------------------------------------------

extern "C" void kernel_launch(void* const* d_in, const int* in_sizes, int n_in,
                              void* d_out, int out_size) {
    const float* x    = (const float*)d_in[0];
    const int*   src  = (const int*)  d_in[1];
    const int*   dst  = (const int*)  d_in[2];
    const int*   psrc = (const int*)  d_in[3];
    const int*   pdst = (const int*)  d_in[4];
    const float* W1   = (const float*)d_in[5];
    const float* b1   = (const float*)d_in[6];
    const float* W2   = (const float*)d_in[7];
    const float* b2   = (const float*)d_in[8];
    const float* Wp   = (const float*)d_in[9];
    const float* bp   = (const float*)d_in[10];
    float* out = (float*)d_out;

    const int TB = 256;
    // degrees
    k_zero_deg<<<(N_NODES + TB - 1) / TB, TB>>>();
    k_degree  <<<(N_EDGES + TB - 1) / TB, TB>>>(src, dst);

    // CSR build (by dst) + norms
    k_scan1<<<NB_SCAN, 256>>>();
    k_scan2<<<1, 512>>>();
    k_scan3_norms<<<(N_NODES + TB - 1) / TB, TB>>>();
    k_bucket<<<(N_EDGES + TB - 1) / TB, TB>>>(src, dst);

    const int AG_BLOCKS = N_NODES / 8;   // 12500, exact

    // layer 1: fused aggregate(x, inline norm_out) + GEMM + relu*norm_out
    k_agg_gemm<0><<<AG_BLOCKS, TB>>>(x, W1, b1);      // -> g_xn

    // layer 2: fused aggregate(g_xn) + GEMM
    k_agg_gemm<1><<<AG_BLOCKS, TB>>>(nullptr, W2, b2); // -> g_h

    // predictor
    k_project<<<(N_NODES + 15) / 16, TB>>>(Wp);
    k_edge_pred<<<(N_PRED + TB - 1) / TB, TB>>>(psrc, pdst, bp, out);
}

// round 10
// speedup vs baseline: 1.5035x; 1.5035x over previous
#include <cuda_runtime.h>
#include <cstdint>

#define N_NODES 100000
#define N_EDGES 1600000
#define N_PRED  500000
#define D       64
#define NB_SCAN 391   // ceil(N_NODES/256)

// ---------------- device scratch (alloc-free rule: static globals) ----------
__device__ int   g_deg_out[N_NODES];
__device__ int   g_deg_in [N_NODES];
__device__ float g_norm_out[N_NODES];
__device__ float g_norm_in [N_NODES];
__device__ int   g_rowstart[N_NODES];
__device__ int   g_cursor  [N_NODES];
__device__ int   g_blocksum[NB_SCAN];
__device__ int   g_csr_src [N_EDGES];
__device__ __align__(16) float g_xn [(size_t)N_NODES * D]; // layer-2 input (pre-scaled)
__device__ __align__(16) float g_agg[(size_t)N_NODES * D]; // aggregated (incl. norm_in)
__device__ __align__(16) float g_h  [(size_t)N_NODES * D]; // layer-2 output
__device__ __align__(16) float g_p  [(size_t)N_NODES * 16];// [pA | pB] per node

// ---------------- degree --------------------------------------------------

__global__ void k_zero_deg() {
    int i = blockIdx.x * blockDim.x + threadIdx.x;
    if (i < N_NODES) { g_deg_out[i] = 0; g_deg_in[i] = 0; }
}

__global__ void k_degree(const int* __restrict__ src, const int* __restrict__ dst) {
    int e = blockIdx.x * blockDim.x + threadIdx.x;
    if (e < N_EDGES) {
        atomicAdd(&g_deg_out[__ldg(&src[e])], 1);
        atomicAdd(&g_deg_in [__ldg(&dst[e])], 1);
    }
}

// ---------------- scan of deg_in -> rowstart --------------------------------
// k_scan1 produces per-block exclusive partials + per-block sums.
// k_scan3_norms (next kernel) sums the needed prefix of g_blocksum itself,
// so the old middle kernel (scan2) is gone. g_blocksum is written by the
// PREVIOUS kernel launch, so reads here need no special ordering.

__global__ void k_scan1() {
    __shared__ int sh[256];
    int i = blockIdx.x * 256 + threadIdx.x;
    int v = (i < N_NODES) ? g_deg_in[i] : 0;
    sh[threadIdx.x] = v;
    __syncthreads();
#pragma unroll
    for (int off = 1; off < 256; off <<= 1) {
        int t = (threadIdx.x >= off) ? sh[threadIdx.x - off] : 0;
        __syncthreads();
        sh[threadIdx.x] += t;
        __syncthreads();
    }
    if (i < N_NODES) g_rowstart[i] = sh[threadIdx.x] - v;   // exclusive within block
    if (threadIdx.x == 255) g_blocksum[blockIdx.x] = sh[255];
}

// finalize rowstart/cursor (adding inter-block offset) AND compute norms.
// Block bid covers nodes [bid*256, bid*256+256); its offset is
// sum(g_blocksum[0..bid-1]), computed by warp 0 and broadcast via smem.
__global__ void k_scan3_norms() {
    __shared__ int s_off;
    const int bid = blockIdx.x;
    if (threadIdx.x < 32) {
        int lane = threadIdx.x;
        int acc = 0;
        for (int j = lane; j < bid; j += 32) acc += g_blocksum[j];
#pragma unroll
        for (int off = 16; off > 0; off >>= 1)
            acc += __shfl_xor_sync(0xffffffffu, acc, off);
        if (lane == 0) s_off = acc;
    }
    __syncthreads();
    int i = bid * 256 + threadIdx.x;
    if (i < N_NODES) {
        int rs = g_rowstart[i] + s_off;
        g_rowstart[i] = rs;
        g_cursor[i] = rs;
        int dou = g_deg_out[i];
        int din = g_deg_in[i];
        g_norm_out[i] = dou > 0 ? rsqrtf((float)dou) : 0.f;
        g_norm_in [i] = din > 0 ? rsqrtf((float)din) : 0.f;
    }
}

// ---------------- CSR bucket fill -------------------------------------------

__global__ void k_bucket(const int* __restrict__ src, const int* __restrict__ dst) {
    int e = blockIdx.x * blockDim.x + threadIdx.x;
    if (e < N_EDGES) {
        int d = __ldg(&dst[e]);
        int pos = atomicAdd(&g_cursor[d], 1);
        g_csr_src[pos] = __ldg(&src[e]);
    }
}

// ---------------- pull-mode aggregation (R5-proven) -------------------------
// One warp per dst node; the two half-warps process neighbors k and k+1
// concurrently, each lane loading a float4 (16 lanes x 16B = 256B row).
// SRC_X=1: read raw x (kernel arg), scale rows by norm_out[src] inline.
// SRC_X=0: read g_xn device global directly (already pre-scaled).
// Epilogue combines half-warps (shfl-xor 16) and applies norm_in.
template <int SRC_X>
__global__ void __launch_bounds__(256)
k_aggregate(const float* __restrict__ xin) {
    int warp = (blockIdx.x * blockDim.x + threadIdx.x) >> 5;
    int lane = threadIdx.x & 31;
    if (warp >= N_NODES) return;

    const float* in = SRC_X ? xin : (const float*)g_xn;
    const int half = lane >> 4;   // which neighbor of the pair
    const int col  = lane & 15;   // float4 column within the row

    int start = g_rowstart[warp];
    int deg   = g_deg_in[warp];
    float4 acc = make_float4(0.f, 0.f, 0.f, 0.f);

    for (int base = 0; base < deg; base += 32) {
        int my = base + lane;
        int s_my = (my < deg) ? __ldg(&g_csr_src[start + my]) : 0;
        int cnt = min(32, deg - base);
#pragma unroll 4
        for (int k2 = 0; k2 < cnt; k2 += 2) {
            int idx = k2 + half;
            int s = __shfl_sync(0xffffffffu, s_my, idx & 31);
            if (idx < cnt) {
                float4 v = ((const float4*)(in + (size_t)s * D))[col];
                if (SRC_X) {
                    float no = __ldg(&g_norm_out[s]);
                    v.x *= no; v.y *= no; v.z *= no; v.w *= no;
                }
                acc.x += v.x; acc.y += v.y; acc.z += v.z; acc.w += v.w;
            }
        }
    }
    acc.x += __shfl_xor_sync(0xffffffffu, acc.x, 16);
    acc.y += __shfl_xor_sync(0xffffffffu, acc.y, 16);
    acc.z += __shfl_xor_sync(0xffffffffu, acc.z, 16);
    acc.w += __shfl_xor_sync(0xffffffffu, acc.w, 16);

    if (half == 0) {
        float ni = g_norm_in[warp];
        acc.x *= ni; acc.y *= ni; acc.z *= ni; acc.w *= ni;
        ((float4*)(g_agg + (size_t)warp * D))[col] = acc;
    }
}

// ---------------- node GEMM update (R5-proven) -------------------------------
// out = f(g_agg @ W + b)   (g_agg already includes norm_in scaling)
// MODE 0: relu, then *norm_out -> g_xn.  MODE 1: plain -> g_h.
template <int MODE>
__global__ void __launch_bounds__(256, 2)
k_node_update(const float* __restrict__ W, const float* __restrict__ b) {
    const int t = threadIdx.x;
    const int c = t & 63;
    const int r = t >> 6;

    float w[D];
#pragma unroll
    for (int kk = 0; kk < D; kk++) w[kk] = __ldg(&W[kk * D + c]);
    const float bc = __ldg(&b[c]);

    __shared__ __align__(16) float vs[4][D];

    for (int base = blockIdx.x * 4; base < N_NODES; base += gridDim.x * 4) {
        int node = base + r;
        bool ok = (node < N_NODES);
        size_t off = (size_t)(ok ? node : 0) * D + c;
        if (ok) vs[r][c] = g_agg[off];
        __syncthreads();

        float acc = bc;
        const float4* vrow = (const float4*)vs[r];
#pragma unroll
        for (int q = 0; q < D / 4; q++) {
            float4 vv = vrow[q];
            acc = fmaf(vv.x, w[4 * q + 0], acc);
            acc = fmaf(vv.y, w[4 * q + 1], acc);
            acc = fmaf(vv.z, w[4 * q + 2], acc);
            acc = fmaf(vv.w, w[4 * q + 3], acc);
        }
        if (ok) {
            if (MODE == 0) {
                acc = fmaxf(acc, 0.f) * g_norm_out[node];
                g_xn[off] = acc;
            } else {
                g_h[off] = acc;
            }
        }
        __syncthreads();
    }
}

// ---------------- predictor --------------------------------------------------
// Per-node projection: g_p[n][0:8] = h[n] @ Wp[0:64], g_p[n][8:16] = h[n] @ Wp[64:128]
__global__ void __launch_bounds__(256, 2)
k_project(const float* __restrict__ Wp) {
    const int t = threadIdx.x;
    const int c  = t & 15;
    const int nl = t >> 4;

    const int rowoff = (c < 8) ? 0 : 64;
    const int cc = c & 7;
    float w[D];
#pragma unroll
    for (int kk = 0; kk < D; kk++) w[kk] = __ldg(&Wp[(rowoff + kk) * 8 + cc]);

    __shared__ __align__(16) float hs[16 * D];

    for (int base = blockIdx.x * 16; base < N_NODES; base += gridDim.x * 16) {
        if (base + (t >> 4) < N_NODES)
            ((float4*)hs)[t] = ((const float4*)(g_h + (size_t)base * D))[t];
        __syncthreads();

        int node = base + nl;
        if (node < N_NODES) {
            float acc = 0.f;
            const float4* vrow = (const float4*)(hs + nl * D);
#pragma unroll
            for (int q = 0; q < D / 4; q++) {
                float4 vv = vrow[q];
                acc = fmaf(vv.x, w[4 * q + 0], acc);
                acc = fmaf(vv.y, w[4 * q + 1], acc);
                acc = fmaf(vv.z, w[4 * q + 2], acc);
                acc = fmaf(vv.w, w[4 * q + 3], acc);
            }
            g_p[(size_t)node * 16 + c] = acc;
        }
        __syncthreads();
    }
}

__global__ void k_edge_pred(const int* __restrict__ psrc, const int* __restrict__ pdst,
                            const float* __restrict__ bp, float* __restrict__ out) {
    int e = blockIdx.x * blockDim.x + threadIdx.x;
    if (e >= N_PRED) return;
    int u = __ldg(&psrc[e]);
    int v = __ldg(&pdst[e]);
    const float4* pa = (const float4*)(g_p + (size_t)u * 16);
    const float4* pb = (const float4*)(g_p + (size_t)v * 16 + 8);
    float4 a0 = pa[0], a1 = pa[1];
    float4 c0 = pb[0], c1 = pb[1];
    float4 bp0 = ((const float4*)bp)[0];
    float4 bp1 = ((const float4*)bp)[1];
    float4 o0 = make_float4(a0.x + c0.x + bp0.x, a0.y + c0.y + bp0.y,
                            a0.z + c0.z + bp0.z, a0.w + c0.w + bp0.w);
    float4 o1 = make_float4(a1.x + c1.x + bp1.x, a1.y + c1.y + bp1.y,
                            a1.z + c1.z + bp1.z, a1.w + c1.w + bp1.w);
    ((float4*)out)[(size_t)e * 2 + 0] = o0;
    ((float4*)out)[(size_t)e * 2 + 1] = o1;
}

// ---------------- launch ----------------------------------------------------

extern "C" void kernel_launch(void* const* d_in, const int* in_sizes, int n_in,
                              void* d_out, int out_size) {
    const float* x    = (const float*)d_in[0];
    const int*   src  = (const int*)  d_in[1];
    const int*   dst  = (const int*)  d_in[2];
    const int*   psrc = (const int*)  d_in[3];
    const int*   pdst = (const int*)  d_in[4];
    const float* W1   = (const float*)d_in[5];
    const float* b1   = (const float*)d_in[6];
    const float* W2   = (const float*)d_in[7];
    const float* b2   = (const float*)d_in[8];
    const float* Wp   = (const float*)d_in[9];
    const float* bp   = (const float*)d_in[10];
    float* out = (float*)d_out;

    const int TB = 256;
    // degrees
    k_zero_deg<<<(N_NODES + TB - 1) / TB, TB>>>();
    k_degree  <<<(N_EDGES + TB - 1) / TB, TB>>>(src, dst);

    // CSR build (by dst) + norms (scan2 folded into scan3_norms)
    k_scan1<<<NB_SCAN, 256>>>();
    k_scan3_norms<<<NB_SCAN, 256>>>();
    k_bucket<<<(N_EDGES + TB - 1) / TB, TB>>>(src, dst);

    const int AGG_BLOCKS = N_NODES * 32 / TB;  // one warp per node, exact

    // layer 1: aggregate raw x with inline norm_out scaling, then GEMM+relu
    k_aggregate<1><<<AGG_BLOCKS, TB>>>(x);
    k_node_update<0><<<1024, TB>>>(W1, b1);    // -> g_xn (relu * norm_out)

    // layer 2: aggregate g_xn (referenced directly in device code)
    k_aggregate<0><<<AGG_BLOCKS, TB>>>(nullptr);
    k_node_update<1><<<1024, TB>>>(W2, b2);    // -> g_h

    // predictor
    k_project<<<(N_NODES + 15) / 16, TB>>>(Wp);
    k_edge_pred<<<(N_PRED + TB - 1) / TB, TB>>>(psrc, pdst, bp, out);
}

// round 12
// speedup vs baseline: 1.5557x; 1.0347x over previous
#include <cuda_runtime.h>
#include <cuda_fp16.h>
#include <cstdint>

#define N_NODES 100000
#define N_EDGES 1600000
#define N_PRED  500000
#define D       64
#define NB_SCAN 391   // ceil(N_NODES/256)

// ---------------- device scratch (alloc-free rule: static globals) ----------
__device__ int   g_deg_out[N_NODES];
__device__ int   g_deg_in [N_NODES];
__device__ float g_norm_out[N_NODES];
__device__ float g_norm_in [N_NODES];
__device__ int   g_rowstart[N_NODES];
__device__ int   g_cursor  [N_NODES];
__device__ int   g_blocksum[NB_SCAN];
__device__ int   g_csr_src [N_EDGES];
__device__ __align__(16) __half g_xh[(size_t)N_NODES * D]; // fp16 messages (both layers)
__device__ __align__(16) float g_agg[(size_t)N_NODES * D]; // aggregated (incl. norm_in), fp32
__device__ __align__(16) float g_h  [(size_t)N_NODES * D]; // layer-2 output, fp32
__device__ __align__(16) float g_p  [(size_t)N_NODES * 16];// [pA | pB] per node

// ---------------- degree --------------------------------------------------

__global__ void k_zero_deg() {
    int i = blockIdx.x * blockDim.x + threadIdx.x;
    if (i < N_NODES) { g_deg_out[i] = 0; g_deg_in[i] = 0; }
}

__global__ void k_degree(const int* __restrict__ src, const int* __restrict__ dst) {
    int e = blockIdx.x * blockDim.x + threadIdx.x;
    if (e < N_EDGES) {
        atomicAdd(&g_deg_out[__ldg(&src[e])], 1);
        atomicAdd(&g_deg_in [__ldg(&dst[e])], 1);
    }
}

// ---------------- scan of deg_in -> rowstart --------------------------------

__global__ void k_scan1() {
    __shared__ int sh[256];
    int i = blockIdx.x * 256 + threadIdx.x;
    int v = (i < N_NODES) ? g_deg_in[i] : 0;
    sh[threadIdx.x] = v;
    __syncthreads();
#pragma unroll
    for (int off = 1; off < 256; off <<= 1) {
        int t = (threadIdx.x >= off) ? sh[threadIdx.x - off] : 0;
        __syncthreads();
        sh[threadIdx.x] += t;
        __syncthreads();
    }
    if (i < N_NODES) g_rowstart[i] = sh[threadIdx.x] - v;   // exclusive within block
    if (threadIdx.x == 255) g_blocksum[blockIdx.x] = sh[255];
}

// finalize rowstart/cursor (adding inter-block offset) AND compute norms.
// g_blocksum was fully written by the PREVIOUS launch (k_scan1); no special
// ordering needed here.
__global__ void k_scan3_norms() {
    __shared__ int s_off;
    const int bid = blockIdx.x;
    if (threadIdx.x < 32) {
        int lane = threadIdx.x;
        int acc = 0;
        for (int j = lane; j < bid; j += 32) acc += g_blocksum[j];
#pragma unroll
        for (int off = 16; off > 0; off >>= 1)
            acc += __shfl_xor_sync(0xffffffffu, acc, off);
        if (lane == 0) s_off = acc;
    }
    __syncthreads();
    int i = bid * 256 + threadIdx.x;
    if (i < N_NODES) {
        int rs = g_rowstart[i] + s_off;
        g_rowstart[i] = rs;
        g_cursor[i] = rs;
        int dou = g_deg_out[i];
        int din = g_deg_in[i];
        g_norm_out[i] = dou > 0 ? rsqrtf((float)dou) : 0.f;
        g_norm_in [i] = din > 0 ? rsqrtf((float)din) : 0.f;
    }
}

// ---------------- CSR bucket fill -------------------------------------------

__global__ void k_bucket(const int* __restrict__ src, const int* __restrict__ dst) {
    int e = blockIdx.x * blockDim.x + threadIdx.x;
    if (e < N_EDGES) {
        int d = __ldg(&dst[e]);
        int pos = atomicAdd(&g_cursor[d], 1);
        g_csr_src[pos] = __ldg(&src[e]);
    }
}

// ---------------- fp16 message prep -----------------------------------------
// g_xh = fp16(x * norm_out), half2 per thread.
__global__ void k_scale_half(const float* __restrict__ x) {
    int i = blockIdx.x * blockDim.x + threadIdx.x;     // over N_NODES * D/2
    if (i < N_NODES * (D / 2)) {
        int node = i >> 5;                              // D/2 = 32
        float no = g_norm_out[node];
        float2 v = ((const float2*)x)[i];
        ((__half2*)g_xh)[i] = __floats2half2_rn(v.x * no, v.y * no);
    }
}

// ---------------- pull-mode aggregation (fp16 gather, fp32 accumulate) ------
// One warp per dst node; half-warps process neighbors k and k+1 concurrently.
// Each lane loads 4 halves (8B); 16 lanes x 8B = 128B row. Epilogue combines
// half-warps (shfl-xor 16) and applies norm_in; result written fp32 to g_agg.
__global__ void __launch_bounds__(256)
k_aggregate() {
    int warp = (blockIdx.x * blockDim.x + threadIdx.x) >> 5;
    int lane = threadIdx.x & 31;
    if (warp >= N_NODES) return;

    const int half = lane >> 4;   // which neighbor of the pair
    const int col  = lane & 15;   // 4-half group within the row

    int start = g_rowstart[warp];
    int deg   = g_deg_in[warp];
    float4 acc = make_float4(0.f, 0.f, 0.f, 0.f);

    for (int base = 0; base < deg; base += 32) {
        int my = base + lane;
        int s_my = (my < deg) ? __ldg(&g_csr_src[start + my]) : 0;
        int cnt = min(32, deg - base);
#pragma unroll 4
        for (int k2 = 0; k2 < cnt; k2 += 2) {
            int idx = k2 + half;
            int s = __shfl_sync(0xffffffffu, s_my, idx & 31);
            if (idx < cnt) {
                const __half2* row = (const __half2*)(g_xh + (size_t)s * D);
                __half2 h0 = row[col * 2 + 0];
                __half2 h1 = row[col * 2 + 1];
                float2 f0 = __half22float2(h0);
                float2 f1 = __half22float2(h1);
                acc.x += f0.x; acc.y += f0.y; acc.z += f1.x; acc.w += f1.y;
            }
        }
    }
    acc.x += __shfl_xor_sync(0xffffffffu, acc.x, 16);
    acc.y += __shfl_xor_sync(0xffffffffu, acc.y, 16);
    acc.z += __shfl_xor_sync(0xffffffffu, acc.z, 16);
    acc.w += __shfl_xor_sync(0xffffffffu, acc.w, 16);

    if (half == 0) {
        float ni = g_norm_in[warp];
        acc.x *= ni; acc.y *= ni; acc.z *= ni; acc.w *= ni;
        ((float4*)(g_agg + (size_t)warp * D))[col] = acc;
    }
}

// ---------------- node GEMM update ------------------------------------------
// out = f(g_agg @ W + b)   (g_agg already includes norm_in scaling)
// MODE 0: relu * norm_out -> g_xh as fp16 (layer-2 messages).
// MODE 1: plain fp32 -> g_h.
template <int MODE>
__global__ void __launch_bounds__(256, 2)
k_node_update(const float* __restrict__ W, const float* __restrict__ b) {
    const int t = threadIdx.x;
    const int c = t & 63;
    const int r = t >> 6;

    float w[D];
#pragma unroll
    for (int kk = 0; kk < D; kk++) w[kk] = __ldg(&W[kk * D + c]);
    const float bc = __ldg(&b[c]);

    __shared__ __align__(16) float vs[4][D];

    for (int base = blockIdx.x * 4; base < N_NODES; base += gridDim.x * 4) {
        int node = base + r;
        bool ok = (node < N_NODES);
        size_t off = (size_t)(ok ? node : 0) * D + c;
        if (ok) vs[r][c] = g_agg[off];
        __syncthreads();

        float acc = bc;
        const float4* vrow = (const float4*)vs[r];
#pragma unroll
        for (int q = 0; q < D / 4; q++) {
            float4 vv = vrow[q];
            acc = fmaf(vv.x, w[4 * q + 0], acc);
            acc = fmaf(vv.y, w[4 * q + 1], acc);
            acc = fmaf(vv.z, w[4 * q + 2], acc);
            acc = fmaf(vv.w, w[4 * q + 3], acc);
        }
        if (ok) {
            if (MODE == 0) {
                acc = fmaxf(acc, 0.f) * g_norm_out[node];
                g_xh[off] = __float2half_rn(acc);
            } else {
                g_h[off] = acc;
            }
        }
        __syncthreads();
    }
}

// ---------------- predictor --------------------------------------------------
// Per-node projection: g_p[n][0:8] = h[n] @ Wp[0:64], g_p[n][8:16] = h[n] @ Wp[64:128]
__global__ void __launch_bounds__(256, 2)
k_project(const float* __restrict__ Wp) {
    const int t = threadIdx.x;
    const int c  = t & 15;
    const int nl = t >> 4;

    const int rowoff = (c < 8) ? 0 : 64;
    const int cc = c & 7;
    float w[D];
#pragma unroll
    for (int kk = 0; kk < D; kk++) w[kk] = __ldg(&Wp[(rowoff + kk) * 8 + cc]);

    __shared__ __align__(16) float hs[16 * D];

    for (int base = blockIdx.x * 16; base < N_NODES; base += gridDim.x * 16) {
        if (base + (t >> 4) < N_NODES)
            ((float4*)hs)[t] = ((const float4*)(g_h + (size_t)base * D))[t];
        __syncthreads();

        int node = base + nl;
        if (node < N_NODES) {
            float acc = 0.f;
            const float4* vrow = (const float4*)(hs + nl * D);
#pragma unroll
            for (int q = 0; q < D / 4; q++) {
                float4 vv = vrow[q];
                acc = fmaf(vv.x, w[4 * q + 0], acc);
                acc = fmaf(vv.y, w[4 * q + 1], acc);
                acc = fmaf(vv.z, w[4 * q + 2], acc);
                acc = fmaf(vv.w, w[4 * q + 3], acc);
            }
            g_p[(size_t)node * 16 + c] = acc;
        }
        __syncthreads();
    }
}

__global__ void k_edge_pred(const int* __restrict__ psrc, const int* __restrict__ pdst,
                            const float* __restrict__ bp, float* __restrict__ out) {
    int e = blockIdx.x * blockDim.x + threadIdx.x;
    if (e >= N_PRED) return;
    int u = __ldg(&psrc[e]);
    int v = __ldg(&pdst[e]);
    const float4* pa = (const float4*)(g_p + (size_t)u * 16);
    const float4* pb = (const float4*)(g_p + (size_t)v * 16 + 8);
    float4 a0 = pa[0], a1 = pa[1];
    float4 c0 = pb[0], c1 = pb[1];
    float4 bp0 = ((const float4*)bp)[0];
    float4 bp1 = ((const float4*)bp)[1];
    float4 o0 = make_float4(a0.x + c0.x + bp0.x, a0.y + c0.y + bp0.y,
                            a0.z + c0.z + bp0.z, a0.w + c0.w + bp0.w);
    float4 o1 = make_float4(a1.x + c1.x + bp1.x, a1.y + c1.y + bp1.y,
                            a1.z + c1.z + bp1.z, a1.w + c1.w + bp1.w);
    ((float4*)out)[(size_t)e * 2 + 0] = o0;
    ((float4*)out)[(size_t)e * 2 + 1] = o1;
}

// ---------------- launch ----------------------------------------------------

extern "C" void kernel_launch(void* const* d_in, const int* in_sizes, int n_in,
                              void* d_out, int out_size) {
    const float* x    = (const float*)d_in[0];
    const int*   src  = (const int*)  d_in[1];
    const int*   dst  = (const int*)  d_in[2];
    const int*   psrc = (const int*)  d_in[3];
    const int*   pdst = (const int*)  d_in[4];
    const float* W1   = (const float*)d_in[5];
    const float* b1   = (const float*)d_in[6];
    const float* W2   = (const float*)d_in[7];
    const float* b2   = (const float*)d_in[8];
    const float* Wp   = (const float*)d_in[9];
    const float* bp   = (const float*)d_in[10];
    float* out = (float*)d_out;

    const int TB = 256;
    // degrees
    k_zero_deg<<<(N_NODES + TB - 1) / TB, TB>>>();
    k_degree  <<<(N_EDGES + TB - 1) / TB, TB>>>(src, dst);

    // CSR build (by dst) + norms
    k_scan1<<<NB_SCAN, 256>>>();
    k_scan3_norms<<<NB_SCAN, 256>>>();
    k_bucket<<<(N_EDGES + TB - 1) / TB, TB>>>(src, dst);

    // fp16 messages for layer 1 (x * norm_out)
    k_scale_half<<<(N_NODES * (D / 2) + TB - 1) / TB, TB>>>(x);

    const int AGG_BLOCKS = N_NODES * 32 / TB;  // one warp per node, exact

    // layer 1
    k_aggregate<<<AGG_BLOCKS, TB>>>();
    k_node_update<0><<<1024, TB>>>(W1, b1);    // -> g_xh (fp16: relu * norm_out)

    // layer 2 (reads g_xh written by layer-1 update)
    k_aggregate<<<AGG_BLOCKS, TB>>>();
    k_node_update<1><<<1024, TB>>>(W2, b2);    // -> g_h (fp32)

    // predictor
    k_project<<<(N_NODES + 15) / 16, TB>>>(Wp);
    k_edge_pred<<<(N_PRED + TB - 1) / TB, TB>>>(psrc, pdst, bp, out);
}

// round 15
// speedup vs baseline: 1.5762x; 1.0132x over previous
#include <cuda_runtime.h>
#include <cuda_fp16.h>
#include <cstdint>

#define N_NODES 100000
#define N_EDGES 1600000
#define N_PRED  500000
#define D       64
#define NB_SCAN 391   // ceil(N_NODES/256)

// ---------------- device scratch (alloc-free rule: static globals) ----------
__device__ int   g_deg_out[N_NODES];
__device__ int   g_deg_in [N_NODES];
__device__ float g_norm_out[N_NODES];
__device__ float g_norm_in [N_NODES];
__device__ int   g_rowstart[N_NODES];
__device__ int   g_cursor  [N_NODES];
__device__ int   g_blocksum[NB_SCAN];
__device__ int   g_csr_src [N_EDGES];
__device__ __align__(16) __half g_xh[(size_t)N_NODES * D]; // fp16 messages; later reused for fp16 h
__device__ __align__(16) float g_agg[(size_t)N_NODES * D]; // aggregated (incl. norm_in), fp32
__device__ __align__(16) float g_p  [(size_t)N_NODES * 16];// [pA | pB] per node

// ---------------- degree --------------------------------------------------

__global__ void k_zero_deg() {
    int i = blockIdx.x * blockDim.x + threadIdx.x;
    if (i < N_NODES) { g_deg_out[i] = 0; g_deg_in[i] = 0; }
}

__global__ void k_degree(const int* __restrict__ src, const int* __restrict__ dst) {
    int e = blockIdx.x * blockDim.x + threadIdx.x;
    if (e < N_EDGES) {
        atomicAdd(&g_deg_out[__ldg(&src[e])], 1);
        atomicAdd(&g_deg_in [__ldg(&dst[e])], 1);
    }
}

// ---------------- scan of deg_in -> rowstart --------------------------------

__global__ void k_scan1() {
    __shared__ int sh[256];
    int i = blockIdx.x * 256 + threadIdx.x;
    int v = (i < N_NODES) ? g_deg_in[i] : 0;
    sh[threadIdx.x] = v;
    __syncthreads();
#pragma unroll
    for (int off = 1; off < 256; off <<= 1) {
        int t = (threadIdx.x >= off) ? sh[threadIdx.x - off] : 0;
        __syncthreads();
        sh[threadIdx.x] += t;
        __syncthreads();
    }
    if (i < N_NODES) g_rowstart[i] = sh[threadIdx.x] - v;   // exclusive within block
    if (threadIdx.x == 255) g_blocksum[blockIdx.x] = sh[255];
}

// finalize rowstart/cursor + norms + fp16 layer-1 message conversion, fused.
// Block bid owns nodes [bid*256, bid*256+256). After computing norms (staged
// in smem), the block converts those nodes' x rows: g_xh = fp16(x*norm_out).
// (g_blocksum fully written by the previous launch; no ordering hazard.)
__global__ void k_scan3_norms_scale(const float* __restrict__ x) {
    __shared__ int   s_off;
    __shared__ float s_no[256];
    const int bid = blockIdx.x;
    const int t   = threadIdx.x;
    if (t < 32) {
        int lane = t;
        int acc = 0;
        for (int j = lane; j < bid; j += 32) acc += g_blocksum[j];
#pragma unroll
        for (int off = 16; off > 0; off >>= 1)
            acc += __shfl_xor_sync(0xffffffffu, acc, off);
        if (lane == 0) s_off = acc;
    }
    __syncthreads();
    int i = bid * 256 + t;
    float no = 0.f;
    if (i < N_NODES) {
        int rs = g_rowstart[i] + s_off;
        g_rowstart[i] = rs;
        g_cursor[i] = rs;
        int dou = g_deg_out[i];
        int din = g_deg_in[i];
        no = dou > 0 ? rsqrtf((float)dou) : 0.f;
        g_norm_out[i] = no;
        g_norm_in [i] = din > 0 ? rsqrtf((float)din) : 0.f;
    }
    s_no[t] = no;
    __syncthreads();

    // convert this block's 256 nodes: 8192 half2, 32 per thread, coalesced.
    // half2 index hi = bid*8192 + j*256 + t; node = hi>>5 = bid*256 + j*8 + (t>>5)
    const size_t base_h2 = (size_t)bid * 8192;
#pragma unroll
    for (int j = 0; j < 32; j++) {
        size_t hi = base_h2 + (size_t)j * 256 + t;
        int local_node = j * 8 + (t >> 5);
        if (bid * 256 + local_node < N_NODES) {
            float non = s_no[local_node];
            float2 v = ((const float2*)x)[hi];
            ((__half2*)g_xh)[hi] = __floats2half2_rn(v.x * non, v.y * non);
        }
    }
}

// ---------------- CSR bucket fill -------------------------------------------

__global__ void k_bucket(const int* __restrict__ src, const int* __restrict__ dst) {
    int e = blockIdx.x * blockDim.x + threadIdx.x;
    if (e < N_EDGES) {
        int d = __ldg(&dst[e]);
        int pos = atomicAdd(&g_cursor[d], 1);
        g_csr_src[pos] = __ldg(&src[e]);
    }
}

// ---------------- pull-mode aggregation (fp16 gather, fp32 accumulate) ------
// One warp per dst node; half-warps process neighbors k and k+1 concurrently.
// Each lane loads 4 halves (8B); 16 lanes x 8B = 128B row. Epilogue combines
// half-warps (shfl-xor 16) and applies norm_in; result written fp32 to g_agg.
__global__ void __launch_bounds__(256)
k_aggregate() {
    int warp = (blockIdx.x * blockDim.x + threadIdx.x) >> 5;
    int lane = threadIdx.x & 31;
    if (warp >= N_NODES) return;

    const int half = lane >> 4;   // which neighbor of the pair
    const int col  = lane & 15;   // 4-half group within the row

    int start = g_rowstart[warp];
    int deg   = g_deg_in[warp];
    float4 acc = make_float4(0.f, 0.f, 0.f, 0.f);

    for (int base = 0; base < deg; base += 32) {
        int my = base + lane;
        int s_my = (my < deg) ? __ldg(&g_csr_src[start + my]) : 0;
        int cnt = min(32, deg - base);
#pragma unroll 4
        for (int k2 = 0; k2 < cnt; k2 += 2) {
            int idx = k2 + half;
            int s = __shfl_sync(0xffffffffu, s_my, idx & 31);
            if (idx < cnt) {
                const __half2* row = (const __half2*)(g_xh + (size_t)s * D);
                __half2 h0 = row[col * 2 + 0];
                __half2 h1 = row[col * 2 + 1];
                float2 f0 = __half22float2(h0);
                float2 f1 = __half22float2(h1);
                acc.x += f0.x; acc.y += f0.y; acc.z += f1.x; acc.w += f1.y;
            }
        }
    }
    acc.x += __shfl_xor_sync(0xffffffffu, acc.x, 16);
    acc.y += __shfl_xor_sync(0xffffffffu, acc.y, 16);
    acc.z += __shfl_xor_sync(0xffffffffu, acc.z, 16);
    acc.w += __shfl_xor_sync(0xffffffffu, acc.w, 16);

    if (half == 0) {
        float ni = g_norm_in[warp];
        acc.x *= ni; acc.y *= ni; acc.z *= ni; acc.w *= ni;
        ((float4*)(g_agg + (size_t)warp * D))[col] = acc;
    }
}

// ---------------- node GEMM update ------------------------------------------
// out = f(g_agg @ W + b)   (g_agg already includes norm_in scaling)
// MODE 0: relu * norm_out -> g_xh fp16 (layer-2 messages).
// MODE 1: plain -> g_xh fp16 (h for predictor; g_xh is dead after agg2).
template <int MODE>
__global__ void __launch_bounds__(256, 2)
k_node_update(const float* __restrict__ W, const float* __restrict__ b) {
    const int t = threadIdx.x;
    const int c = t & 63;
    const int r = t >> 6;

    float w[D];
#pragma unroll
    for (int kk = 0; kk < D; kk++) w[kk] = __ldg(&W[kk * D + c]);
    const float bc = __ldg(&b[c]);

    __shared__ __align__(16) float vs[4][D];

    for (int base = blockIdx.x * 4; base < N_NODES; base += gridDim.x * 4) {
        int node = base + r;
        bool ok = (node < N_NODES);
        size_t off = (size_t)(ok ? node : 0) * D + c;
        if (ok) vs[r][c] = g_agg[off];
        __syncthreads();

        float acc = bc;
        const float4* vrow = (const float4*)vs[r];
#pragma unroll
        for (int q = 0; q < D / 4; q++) {
            float4 vv = vrow[q];
            acc = fmaf(vv.x, w[4 * q + 0], acc);
            acc = fmaf(vv.y, w[4 * q + 1], acc);
            acc = fmaf(vv.z, w[4 * q + 2], acc);
            acc = fmaf(vv.w, w[4 * q + 3], acc);
        }
        if (ok) {
            if (MODE == 0) acc = fmaxf(acc, 0.f) * g_norm_out[node];
            g_xh[off] = __float2half_rn(acc);
        }
        __syncthreads();
    }
}

// ---------------- predictor --------------------------------------------------
// h is fp16 in g_xh. Per-node projection:
// g_p[n][0:8] = h[n] @ Wp[0:64], g_p[n][8:16] = h[n] @ Wp[64:128]
__global__ void __launch_bounds__(256, 2)
k_project(const float* __restrict__ Wp) {
    const int t = threadIdx.x;
    const int c  = t & 15;
    const int nl = t >> 4;

    const int rowoff = (c < 8) ? 0 : 64;
    const int cc = c & 7;
    float w[D];
#pragma unroll
    for (int kk = 0; kk < D; kk++) w[kk] = __ldg(&Wp[(rowoff + kk) * 8 + cc]);

    __shared__ __align__(16) float hs[16 * D];

    for (int base = blockIdx.x * 16; base < N_NODES; base += gridDim.x * 16) {
        // stage 16 fp16 rows = 1024 halves = 128 uint4. ONLY threads t<128
        // participate: thread t loads uint4 t (8 halves of row t>>3),
        // converts to fp32 into hs[t*8 .. t*8+8).
        if (t < 128 && (base + (t >> 3)) < N_NODES) {
            uint4 raw = ((const uint4*)(g_xh + (size_t)base * D))[t];
            __half2* hp = (__half2*)&raw;
            float2 f0 = __half22float2(hp[0]);
            float2 f1 = __half22float2(hp[1]);
            float2 f2 = __half22float2(hp[2]);
            float2 f3 = __half22float2(hp[3]);
            float* dstp = hs + t * 8;
            dstp[0] = f0.x; dstp[1] = f0.y; dstp[2] = f1.x; dstp[3] = f1.y;
            dstp[4] = f2.x; dstp[5] = f2.y; dstp[6] = f3.x; dstp[7] = f3.y;
        }
        __syncthreads();

        int node = base + nl;
        if (node < N_NODES) {
            float acc = 0.f;
            const float4* vrow = (const float4*)(hs + nl * D);
#pragma unroll
            for (int q = 0; q < D / 4; q++) {
                float4 vv = vrow[q];
                acc = fmaf(vv.x, w[4 * q + 0], acc);
                acc = fmaf(vv.y, w[4 * q + 1], acc);
                acc = fmaf(vv.z, w[4 * q + 2], acc);
                acc = fmaf(vv.w, w[4 * q + 3], acc);
            }
            g_p[(size_t)node * 16 + c] = acc;
        }
        __syncthreads();
    }
}

__global__ void k_edge_pred(const int* __restrict__ psrc, const int* __restrict__ pdst,
                            const float* __restrict__ bp, float* __restrict__ out) {
    int e = blockIdx.x * blockDim.x + threadIdx.x;
    if (e >= N_PRED) return;
    int u = __ldg(&psrc[e]);
    int v = __ldg(&pdst[e]);
    const float4* pa = (const float4*)(g_p + (size_t)u * 16);
    const float4* pb = (const float4*)(g_p + (size_t)v * 16 + 8);
    float4 a0 = pa[0], a1 = pa[1];
    float4 c0 = pb[0], c1 = pb[1];
    float4 bp0 = ((const float4*)bp)[0];
    float4 bp1 = ((const float4*)bp)[1];
    float4 o0 = make_float4(a0.x + c0.x + bp0.x, a0.y + c0.y + bp0.y,
                            a0.z + c0.z + bp0.z, a0.w + c0.w + bp0.w);
    float4 o1 = make_float4(a1.x + c1.x + bp1.x, a1.y + c1.y + bp1.y,
                            a1.z + c1.z + bp1.z, a1.w + c1.w + bp1.w);
    ((float4*)out)[(size_t)e * 2 + 0] = o0;
    ((float4*)out)[(size_t)e * 2 + 1] = o1;
}

// ---------------- launch ----------------------------------------------------

extern "C" void kernel_launch(void* const* d_in, const int* in_sizes, int n_in,
                              void* d_out, int out_size) {
    const float* x    = (const float*)d_in[0];
    const int*   src  = (const int*)  d_in[1];
    const int*   dst  = (const int*)  d_in[2];
    const int*   psrc = (const int*)  d_in[3];
    const int*   pdst = (const int*)  d_in[4];
    const float* W1   = (const float*)d_in[5];
    const float* b1   = (const float*)d_in[6];
    const float* W2   = (const float*)d_in[7];
    const float* b2   = (const float*)d_in[8];
    const float* Wp   = (const float*)d_in[9];
    const float* bp   = (const float*)d_in[10];
    float* out = (float*)d_out;

    const int TB = 256;
    // degrees
    k_zero_deg<<<(N_NODES + TB - 1) / TB, TB>>>();
    k_degree  <<<(N_EDGES + TB - 1) / TB, TB>>>(src, dst);

    // CSR build (by dst) + norms + fp16 layer-1 message conversion (fused)
    k_scan1<<<NB_SCAN, 256>>>();
    k_scan3_norms_scale<<<NB_SCAN, 256>>>(x);
    k_bucket<<<(N_EDGES + TB - 1) / TB, TB>>>(src, dst);

    const int AGG_BLOCKS = N_NODES * 32 / TB;  // one warp per node, exact

    // layer 1
    k_aggregate<<<AGG_BLOCKS, TB>>>();
    k_node_update<0><<<1024, TB>>>(W1, b1);    // -> g_xh (fp16: relu * norm_out)

    // layer 2 (reads g_xh written by layer-1 update)
    k_aggregate<<<AGG_BLOCKS, TB>>>();
    k_node_update<1><<<1024, TB>>>(W2, b2);    // -> g_xh (fp16 h)

    // predictor
    k_project<<<(N_NODES + 15) / 16, TB>>>(Wp);
    k_edge_pred<<<(N_PRED + TB - 1) / TB, TB>>>(psrc, pdst, bp, out);
}

// round 16
// speedup vs baseline: 1.5776x; 1.0009x over previous
#include <cuda_runtime.h>
#include <cuda_fp16.h>
#include <cstdint>

#define N_NODES 100000
#define N_EDGES 1600000
#define N_PRED  500000
#define D       64
#define NB_SCAN 391   // ceil(N_NODES/256)

// ---------------- device scratch (alloc-free rule: static globals) ----------
__device__ int   g_deg_out[N_NODES];   // zero at start of every run (reset by k_edge_pred)
__device__ int   g_deg_in [N_NODES];
__device__ float g_norm_out[N_NODES];
__device__ float g_norm_in [N_NODES];
__device__ int   g_rowstart[N_NODES];
__device__ int   g_cursor  [N_NODES];
__device__ int   g_blocksum[NB_SCAN];
__device__ int   g_csr_src [N_EDGES];
__device__ __align__(16) __half g_xh[(size_t)N_NODES * D]; // fp16 messages; later reused for fp16 h
__device__ __align__(16) float g_agg[(size_t)N_NODES * D]; // aggregated (incl. norm_in), fp32
__device__ __align__(16) float g_p  [(size_t)N_NODES * 16];// [pA | pB] per node

// ---------------- degree --------------------------------------------------

__global__ void k_degree(const int* __restrict__ src, const int* __restrict__ dst) {
    int e = blockIdx.x * blockDim.x + threadIdx.x;
    if (e < N_EDGES) {
        atomicAdd(&g_deg_out[__ldg(&src[e])], 1);
        atomicAdd(&g_deg_in [__ldg(&dst[e])], 1);
    }
}

// ---------------- scan of deg_in -> rowstart --------------------------------

__global__ void k_scan1() {
    __shared__ int sh[256];
    int i = blockIdx.x * 256 + threadIdx.x;
    int v = (i < N_NODES) ? g_deg_in[i] : 0;
    sh[threadIdx.x] = v;
    __syncthreads();
#pragma unroll
    for (int off = 1; off < 256; off <<= 1) {
        int t = (threadIdx.x >= off) ? sh[threadIdx.x - off] : 0;
        __syncthreads();
        sh[threadIdx.x] += t;
        __syncthreads();
    }
    if (i < N_NODES) g_rowstart[i] = sh[threadIdx.x] - v;   // exclusive within block
    if (threadIdx.x == 255) g_blocksum[blockIdx.x] = sh[255];
}

// finalize rowstart/cursor + norms + fp16 layer-1 message conversion, fused.
// Block bid owns nodes [bid*256, bid*256+256). After computing norms (staged
// in smem), the block converts those nodes' x rows: g_xh = fp16(x*norm_out).
__global__ void k_scan3_norms_scale(const float* __restrict__ x) {
    __shared__ int   s_off;
    __shared__ float s_no[256];
    const int bid = blockIdx.x;
    const int t   = threadIdx.x;
    if (t < 32) {
        int lane = t;
        int acc = 0;
        for (int j = lane; j < bid; j += 32) acc += g_blocksum[j];
#pragma unroll
        for (int off = 16; off > 0; off >>= 1)
            acc += __shfl_xor_sync(0xffffffffu, acc, off);
        if (lane == 0) s_off = acc;
    }
    __syncthreads();
    int i = bid * 256 + t;
    float no = 0.f;
    if (i < N_NODES) {
        int rs = g_rowstart[i] + s_off;
        g_rowstart[i] = rs;
        g_cursor[i] = rs;
        int dou = g_deg_out[i];
        int din = g_deg_in[i];
        no = dou > 0 ? rsqrtf((float)dou) : 0.f;
        g_norm_out[i] = no;
        g_norm_in [i] = din > 0 ? rsqrtf((float)din) : 0.f;
    }
    s_no[t] = no;
    __syncthreads();

    // convert this block's 256 nodes: 8192 half2, 32 per thread, coalesced.
    const size_t base_h2 = (size_t)bid * 8192;
#pragma unroll
    for (int j = 0; j < 32; j++) {
        size_t hi = base_h2 + (size_t)j * 256 + t;
        int local_node = j * 8 + (t >> 5);
        if (bid * 256 + local_node < N_NODES) {
            float non = s_no[local_node];
            float2 v = ((const float2*)x)[hi];
            ((__half2*)g_xh)[hi] = __floats2half2_rn(v.x * non, v.y * non);
        }
    }
}

// ---------------- CSR bucket fill -------------------------------------------

__global__ void k_bucket(const int* __restrict__ src, const int* __restrict__ dst) {
    int e = blockIdx.x * blockDim.x + threadIdx.x;
    if (e < N_EDGES) {
        int d = __ldg(&dst[e]);
        int pos = atomicAdd(&g_cursor[d], 1);
        g_csr_src[pos] = __ldg(&src[e]);
    }
}

// ---------------- pull-mode aggregation (wide fp16 gather) -------------------
// One warp per dst node; FOUR neighbors processed concurrently: quarter =
// lane>>3 selects the neighbor, col8 = lane&7 the 16B (8-half) group, so each
// lane issues one LDG.128 per neighbor-quad. unroll 8 => up to 8 independent
// 16B loads per lane in flight (4x the bytes-in-flight of the old scheme).
// Epilogue combines quarters (shfl-xor 8,16) and applies norm_in.
__global__ void __launch_bounds__(256)
k_aggregate() {
    int warp = (blockIdx.x * blockDim.x + threadIdx.x) >> 5;
    int lane = threadIdx.x & 31;
    if (warp >= N_NODES) return;

    const int quarter = lane >> 3;   // neighbor slot within quad
    const int col8    = lane & 7;    // 8-half (16B) group within row

    int start = g_rowstart[warp];
    int deg   = g_deg_in[warp];
    float acc[8];
#pragma unroll
    for (int j = 0; j < 8; j++) acc[j] = 0.f;

    for (int base = 0; base < deg; base += 32) {
        int my = base + lane;
        int s_my = (my < deg) ? __ldg(&g_csr_src[start + my]) : 0;
        int cnt = min(32, deg - base);
#pragma unroll 8
        for (int k4 = 0; k4 < cnt; k4 += 4) {
            int idx = k4 + quarter;
            int s = __shfl_sync(0xffffffffu, s_my, idx & 31);
            if (idx < cnt) {
                uint4 raw = ((const uint4*)(g_xh + (size_t)s * D))[col8];
                __half2* hp = (__half2*)&raw;
#pragma unroll
                for (int j = 0; j < 4; j++) {
                    float2 f = __half22float2(hp[j]);
                    acc[2 * j]     += f.x;
                    acc[2 * j + 1] += f.y;
                }
            }
        }
    }
    // combine the four quarters (disjoint neighbor subsets, same columns)
#pragma unroll
    for (int j = 0; j < 8; j++) {
        acc[j] += __shfl_xor_sync(0xffffffffu, acc[j], 8);
        acc[j] += __shfl_xor_sync(0xffffffffu, acc[j], 16);
    }
    if (quarter == 0) {
        float ni = g_norm_in[warp];
        float4* dst = (float4*)(g_agg + (size_t)warp * D + col8 * 8);
        dst[0] = make_float4(acc[0] * ni, acc[1] * ni, acc[2] * ni, acc[3] * ni);
        dst[1] = make_float4(acc[4] * ni, acc[5] * ni, acc[6] * ni, acc[7] * ni);
    }
}

// ---------------- node GEMM update ------------------------------------------
// out = f(g_agg @ W + b)   (g_agg already includes norm_in scaling)
// MODE 0: relu * norm_out -> g_xh fp16 (layer-2 messages).
// MODE 1: plain -> g_xh fp16 (h for predictor; g_xh is dead after agg2).
template <int MODE>
__global__ void __launch_bounds__(256, 2)
k_node_update(const float* __restrict__ W, const float* __restrict__ b) {
    const int t = threadIdx.x;
    const int c = t & 63;
    const int r = t >> 6;

    float w[D];
#pragma unroll
    for (int kk = 0; kk < D; kk++) w[kk] = __ldg(&W[kk * D + c]);
    const float bc = __ldg(&b[c]);

    __shared__ __align__(16) float vs[4][D];

    for (int base = blockIdx.x * 4; base < N_NODES; base += gridDim.x * 4) {
        int node = base + r;
        bool ok = (node < N_NODES);
        size_t off = (size_t)(ok ? node : 0) * D + c;
        if (ok) vs[r][c] = g_agg[off];
        __syncthreads();

        float acc = bc;
        const float4* vrow = (const float4*)vs[r];
#pragma unroll
        for (int q = 0; q < D / 4; q++) {
            float4 vv = vrow[q];
            acc = fmaf(vv.x, w[4 * q + 0], acc);
            acc = fmaf(vv.y, w[4 * q + 1], acc);
            acc = fmaf(vv.z, w[4 * q + 2], acc);
            acc = fmaf(vv.w, w[4 * q + 3], acc);
        }
        if (ok) {
            if (MODE == 0) acc = fmaxf(acc, 0.f) * g_norm_out[node];
            g_xh[off] = __float2half_rn(acc);
        }
        __syncthreads();
    }
}

// ---------------- predictor --------------------------------------------------
// h is fp16 in g_xh. Per-node projection:
// g_p[n][0:8] = h[n] @ Wp[0:64], g_p[n][8:16] = h[n] @ Wp[64:128]
__global__ void __launch_bounds__(256, 2)
k_project(const float* __restrict__ Wp) {
    const int t = threadIdx.x;
    const int c  = t & 15;
    const int nl = t >> 4;

    const int rowoff = (c < 8) ? 0 : 64;
    const int cc = c & 7;
    float w[D];
#pragma unroll
    for (int kk = 0; kk < D; kk++) w[kk] = __ldg(&Wp[(rowoff + kk) * 8 + cc]);

    __shared__ __align__(16) float hs[16 * D];

    for (int base = blockIdx.x * 16; base < N_NODES; base += gridDim.x * 16) {
        // stage 16 fp16 rows = 1024 halves = 128 uint4; threads t<128 only.
        if (t < 128 && (base + (t >> 3)) < N_NODES) {
            uint4 raw = ((const uint4*)(g_xh + (size_t)base * D))[t];
            __half2* hp = (__half2*)&raw;
            float2 f0 = __half22float2(hp[0]);
            float2 f1 = __half22float2(hp[1]);
            float2 f2 = __half22float2(hp[2]);
            float2 f3 = __half22float2(hp[3]);
            float* dstp = hs + t * 8;
            dstp[0] = f0.x; dstp[1] = f0.y; dstp[2] = f1.x; dstp[3] = f1.y;
            dstp[4] = f2.x; dstp[5] = f2.y; dstp[6] = f3.x; dstp[7] = f3.y;
        }
        __syncthreads();

        int node = base + nl;
        if (node < N_NODES) {
            float acc = 0.f;
            const float4* vrow = (const float4*)(hs + nl * D);
#pragma unroll
            for (int q = 0; q < D / 4; q++) {
                float4 vv = vrow[q];
                acc = fmaf(vv.x, w[4 * q + 0], acc);
                acc = fmaf(vv.y, w[4 * q + 1], acc);
                acc = fmaf(vv.z, w[4 * q + 2], acc);
                acc = fmaf(vv.w, w[4 * q + 3], acc);
            }
            g_p[(size_t)node * 16 + c] = acc;
        }
        __syncthreads();
    }
}

// Final edge scores; also resets the degree arrays for the next run (device
// globals start zero-initialized, and every run re-zeroes them here, so the
// "deg arrays are zero at sequence start" invariant holds for every replay).
__global__ void k_edge_pred(const int* __restrict__ psrc, const int* __restrict__ pdst,
                            const float* __restrict__ bp, float* __restrict__ out) {
    int e = blockIdx.x * blockDim.x + threadIdx.x;
    if (e < N_NODES) { g_deg_out[e] = 0; g_deg_in[e] = 0; }
    if (e >= N_PRED) return;
    int u = __ldg(&psrc[e]);
    int v = __ldg(&pdst[e]);
    const float4* pa = (const float4*)(g_p + (size_t)u * 16);
    const float4* pb = (const float4*)(g_p + (size_t)v * 16 + 8);
    float4 a0 = pa[0], a1 = pa[1];
    float4 c0 = pb[0], c1 = pb[1];
    float4 bp0 = ((const float4*)bp)[0];
    float4 bp1 = ((const float4*)bp)[1];
    float4 o0 = make_float4(a0.x + c0.x + bp0.x, a0.y + c0.y + bp0.y,
                            a0.z + c0.z + bp0.z, a0.w + c0.w + bp0.w);
    float4 o1 = make_float4(a1.x + c1.x + bp1.x, a1.y + c1.y + bp1.y,
                            a1.z + c1.z + bp1.z, a1.w + c1.w + bp1.w);
    ((float4*)out)[(size_t)e * 2 + 0] = o0;
    ((float4*)out)[(size_t)e * 2 + 1] = o1;
}

// ---------------- launch ----------------------------------------------------

extern "C" void kernel_launch(void* const* d_in, const int* in_sizes, int n_in,
                              void* d_out, int out_size) {
    const float* x    = (const float*)d_in[0];
    const int*   src  = (const int*)  d_in[1];
    const int*   dst  = (const int*)  d_in[2];
    const int*   psrc = (const int*)  d_in[3];
    const int*   pdst = (const int*)  d_in[4];
    const float* W1   = (const float*)d_in[5];
    const float* b1   = (const float*)d_in[6];
    const float* W2   = (const float*)d_in[7];
    const float* b2   = (const float*)d_in[8];
    const float* Wp   = (const float*)d_in[9];
    const float* bp   = (const float*)d_in[10];
    float* out = (float*)d_out;

    const int TB = 256;
    // degrees (arrays arrive zeroed: zero-init at load + reset in k_edge_pred)
    k_degree<<<(N_EDGES + TB - 1) / TB, TB>>>(src, dst);

    // CSR build (by dst) + norms + fp16 layer-1 message conversion (fused)
    k_scan1<<<NB_SCAN, 256>>>();
    k_scan3_norms_scale<<<NB_SCAN, 256>>>(x);
    k_bucket<<<(N_EDGES + TB - 1) / TB, TB>>>(src, dst);

    const int AGG_BLOCKS = N_NODES * 32 / TB;  // one warp per node, exact

    // layer 1
    k_aggregate<<<AGG_BLOCKS, TB>>>();
    k_node_update<0><<<1024, TB>>>(W1, b1);    // -> g_xh (fp16: relu * norm_out)

    // layer 2 (reads g_xh written by layer-1 update)
    k_aggregate<<<AGG_BLOCKS, TB>>>();
    k_node_update<1><<<1024, TB>>>(W2, b2);    // -> g_xh (fp16 h)

    // predictor (k_edge_pred also resets degree arrays for the next run)
    k_project<<<(N_NODES + 15) / 16, TB>>>(Wp);
    k_edge_pred<<<(N_PRED + TB - 1) / TB, TB>>>(psrc, pdst, bp, out);
}

// round 17
// speedup vs baseline: 1.5941x; 1.0105x over previous
#include <cuda_runtime.h>
#include <cuda_fp16.h>
#include <cstdint>

#define N_NODES 100000
#define N_EDGES 1600000
#define N_PRED  500000
#define D       64
#define NB_SCAN 391   // ceil(N_NODES/256)

// ---------------- device scratch (alloc-free rule: static globals) ----------
__device__ int   g_deg_out[N_NODES];   // zero at start of every run (reset by k_edge_pred)
__device__ int   g_deg_in [N_NODES];
__device__ float g_norm_out[N_NODES];
__device__ float g_norm_in [N_NODES];
__device__ int   g_rowstart[N_NODES];
__device__ int   g_blocksum[NB_SCAN];
__device__ int   g_rank    [N_EDGES];  // edge's rank within its dst bucket
__device__ int   g_csr_src [N_EDGES];
__device__ __align__(16) __half g_xh[(size_t)N_NODES * D]; // fp16 messages; later reused for fp16 h
__device__ __align__(16) float g_agg[(size_t)N_NODES * D]; // aggregated (incl. norm_in), fp32
__device__ __align__(16) float g_p  [(size_t)N_NODES * 16];// [pA | pB] per node

// ---------------- degree (also emits per-edge dst-bucket rank) ---------------

__global__ void k_degree(const int* __restrict__ src, const int* __restrict__ dst) {
    int e = blockIdx.x * blockDim.x + threadIdx.x;
    if (e < N_EDGES) {
        atomicAdd(&g_deg_out[__ldg(&src[e])], 1);
        int r = atomicAdd(&g_deg_in[__ldg(&dst[e])], 1);
        g_rank[e] = r;                      // rank of edge e within dst bucket
    }
}

// ---------------- scan of deg_in -> rowstart --------------------------------

__global__ void k_scan1() {
    __shared__ int sh[256];
    int i = blockIdx.x * 256 + threadIdx.x;
    int v = (i < N_NODES) ? g_deg_in[i] : 0;
    sh[threadIdx.x] = v;
    __syncthreads();
#pragma unroll
    for (int off = 1; off < 256; off <<= 1) {
        int t = (threadIdx.x >= off) ? sh[threadIdx.x - off] : 0;
        __syncthreads();
        sh[threadIdx.x] += t;
        __syncthreads();
    }
    if (i < N_NODES) g_rowstart[i] = sh[threadIdx.x] - v;   // exclusive within block
    if (threadIdx.x == 255) g_blocksum[blockIdx.x] = sh[255];
}

// finalize rowstart + norms + fp16 layer-1 message conversion, fused.
// Block bid owns nodes [bid*256, bid*256+256). After computing norms (staged
// in smem), the block converts those nodes' x rows: g_xh = fp16(x*norm_out).
__global__ void k_scan3_norms_scale(const float* __restrict__ x) {
    __shared__ int   s_off;
    __shared__ float s_no[256];
    const int bid = blockIdx.x;
    const int t   = threadIdx.x;
    if (t < 32) {
        int lane = t;
        int acc = 0;
        for (int j = lane; j < bid; j += 32) acc += g_blocksum[j];
#pragma unroll
        for (int off = 16; off > 0; off >>= 1)
            acc += __shfl_xor_sync(0xffffffffu, acc, off);
        if (lane == 0) s_off = acc;
    }
    __syncthreads();
    int i = bid * 256 + t;
    float no = 0.f;
    if (i < N_NODES) {
        g_rowstart[i] += s_off;
        int dou = g_deg_out[i];
        int din = g_deg_in[i];
        no = dou > 0 ? rsqrtf((float)dou) : 0.f;
        g_norm_out[i] = no;
        g_norm_in [i] = din > 0 ? rsqrtf((float)din) : 0.f;
    }
    s_no[t] = no;
    __syncthreads();

    // convert this block's 256 nodes: 8192 half2, 32 per thread, coalesced.
    const size_t base_h2 = (size_t)bid * 8192;
#pragma unroll
    for (int j = 0; j < 32; j++) {
        size_t hi = base_h2 + (size_t)j * 256 + t;
        int local_node = j * 8 + (t >> 5);
        if (bid * 256 + local_node < N_NODES) {
            float non = s_no[local_node];
            float2 v = ((const float2*)x)[hi];
            ((__half2*)g_xh)[hi] = __floats2half2_rn(v.x * non, v.y * non);
        }
    }
}

// ---------------- CSR bucket fill (atomic-free: rowstart + precomputed rank) -

__global__ void k_bucket(const int* __restrict__ src, const int* __restrict__ dst) {
    int e = blockIdx.x * blockDim.x + threadIdx.x;
    if (e < N_EDGES) {
        int d = __ldg(&dst[e]);
        int pos = __ldg(&g_rowstart[d]) + g_rank[e];
        g_csr_src[pos] = __ldg(&src[e]);
    }
}

// ---------------- pull-mode aggregation (wide fp16 gather) -------------------
// One warp per dst node; four neighbors processed concurrently: quarter =
// lane>>3 selects the neighbor, col8 = lane&7 the 16B (8-half) group; each
// lane issues one LDG.128 per neighbor-quad. Epilogue combines quarters
// (shfl-xor 8,16) and applies norm_in.
__global__ void __launch_bounds__(256)
k_aggregate() {
    int warp = (blockIdx.x * blockDim.x + threadIdx.x) >> 5;
    int lane = threadIdx.x & 31;
    if (warp >= N_NODES) return;

    const int quarter = lane >> 3;   // neighbor slot within quad
    const int col8    = lane & 7;    // 8-half (16B) group within row

    int start = g_rowstart[warp];
    int deg   = g_deg_in[warp];
    float acc[8];
#pragma unroll
    for (int j = 0; j < 8; j++) acc[j] = 0.f;

    for (int base = 0; base < deg; base += 32) {
        int my = base + lane;
        int s_my = (my < deg) ? __ldg(&g_csr_src[start + my]) : 0;
        int cnt = min(32, deg - base);
#pragma unroll 8
        for (int k4 = 0; k4 < cnt; k4 += 4) {
            int idx = k4 + quarter;
            int s = __shfl_sync(0xffffffffu, s_my, idx & 31);
            if (idx < cnt) {
                uint4 raw = ((const uint4*)(g_xh + (size_t)s * D))[col8];
                __half2* hp = (__half2*)&raw;
#pragma unroll
                for (int j = 0; j < 4; j++) {
                    float2 f = __half22float2(hp[j]);
                    acc[2 * j]     += f.x;
                    acc[2 * j + 1] += f.y;
                }
            }
        }
    }
#pragma unroll
    for (int j = 0; j < 8; j++) {
        acc[j] += __shfl_xor_sync(0xffffffffu, acc[j], 8);
        acc[j] += __shfl_xor_sync(0xffffffffu, acc[j], 16);
    }
    if (quarter == 0) {
        float ni = g_norm_in[warp];
        float4* dst = (float4*)(g_agg + (size_t)warp * D + col8 * 8);
        dst[0] = make_float4(acc[0] * ni, acc[1] * ni, acc[2] * ni, acc[3] * ni);
        dst[1] = make_float4(acc[4] * ni, acc[5] * ni, acc[6] * ni, acc[7] * ni);
    }
}

// ---------------- node GEMM update ------------------------------------------
// out = f(g_agg @ W + b)   (g_agg already includes norm_in scaling)
// MODE 0: relu * norm_out -> g_xh fp16 (layer-2 messages).
// MODE 1: plain -> g_xh fp16 (h for predictor; g_xh is dead after agg2).
template <int MODE>
__global__ void __launch_bounds__(256, 2)
k_node_update(const float* __restrict__ W, const float* __restrict__ b) {
    const int t = threadIdx.x;
    const int c = t & 63;
    const int r = t >> 6;

    float w[D];
#pragma unroll
    for (int kk = 0; kk < D; kk++) w[kk] = __ldg(&W[kk * D + c]);
    const float bc = __ldg(&b[c]);

    __shared__ __align__(16) float vs[4][D];

    for (int base = blockIdx.x * 4; base < N_NODES; base += gridDim.x * 4) {
        int node = base + r;
        bool ok = (node < N_NODES);
        size_t off = (size_t)(ok ? node : 0) * D + c;
        if (ok) vs[r][c] = g_agg[off];
        __syncthreads();

        float acc = bc;
        const float4* vrow = (const float4*)vs[r];
#pragma unroll
        for (int q = 0; q < D / 4; q++) {
            float4 vv = vrow[q];
            acc = fmaf(vv.x, w[4 * q + 0], acc);
            acc = fmaf(vv.y, w[4 * q + 1], acc);
            acc = fmaf(vv.z, w[4 * q + 2], acc);
            acc = fmaf(vv.w, w[4 * q + 3], acc);
        }
        if (ok) {
            if (MODE == 0) acc = fmaxf(acc, 0.f) * g_norm_out[node];
            g_xh[off] = __float2half_rn(acc);
        }
        __syncthreads();
    }
}

// ---------------- predictor --------------------------------------------------
// h is fp16 in g_xh. Per-node projection:
// g_p[n][0:8] = h[n] @ Wp[0:64], g_p[n][8:16] = h[n] @ Wp[64:128]
__global__ void __launch_bounds__(256, 2)
k_project(const float* __restrict__ Wp) {
    const int t = threadIdx.x;
    const int c  = t & 15;
    const int nl = t >> 4;

    const int rowoff = (c < 8) ? 0 : 64;
    const int cc = c & 7;
    float w[D];
#pragma unroll
    for (int kk = 0; kk < D; kk++) w[kk] = __ldg(&Wp[(rowoff + kk) * 8 + cc]);

    __shared__ __align__(16) float hs[16 * D];

    for (int base = blockIdx.x * 16; base < N_NODES; base += gridDim.x * 16) {
        // stage 16 fp16 rows = 1024 halves = 128 uint4; threads t<128 only.
        if (t < 128 && (base + (t >> 3)) < N_NODES) {
            uint4 raw = ((const uint4*)(g_xh + (size_t)base * D))[t];
            __half2* hp = (__half2*)&raw;
            float2 f0 = __half22float2(hp[0]);
            float2 f1 = __half22float2(hp[1]);
            float2 f2 = __half22float2(hp[2]);
            float2 f3 = __half22float2(hp[3]);
            float* dstp = hs + t * 8;
            dstp[0] = f0.x; dstp[1] = f0.y; dstp[2] = f1.x; dstp[3] = f1.y;
            dstp[4] = f2.x; dstp[5] = f2.y; dstp[6] = f3.x; dstp[7] = f3.y;
        }
        __syncthreads();

        int node = base + nl;
        if (node < N_NODES) {
            float acc = 0.f;
            const float4* vrow = (const float4*)(hs + nl * D);
#pragma unroll
            for (int q = 0; q < D / 4; q++) {
                float4 vv = vrow[q];
                acc = fmaf(vv.x, w[4 * q + 0], acc);
                acc = fmaf(vv.y, w[4 * q + 1], acc);
                acc = fmaf(vv.z, w[4 * q + 2], acc);
                acc = fmaf(vv.w, w[4 * q + 3], acc);
            }
            g_p[(size_t)node * 16 + c] = acc;
        }
        __syncthreads();
    }
}

// Final edge scores; also resets the degree arrays for the next run (device
// globals start zero-initialized, and every run re-zeroes them here, so the
// "deg arrays are zero at sequence start" invariant holds for every replay).
__global__ void k_edge_pred(const int* __restrict__ psrc, const int* __restrict__ pdst,
                            const float* __restrict__ bp, float* __restrict__ out) {
    int e = blockIdx.x * blockDim.x + threadIdx.x;
    if (e < N_NODES) { g_deg_out[e] = 0; g_deg_in[e] = 0; }
    if (e >= N_PRED) return;
    int u = __ldg(&psrc[e]);
    int v = __ldg(&pdst[e]);
    const float4* pa = (const float4*)(g_p + (size_t)u * 16);
    const float4* pb = (const float4*)(g_p + (size_t)v * 16 + 8);
    float4 a0 = pa[0], a1 = pa[1];
    float4 c0 = pb[0], c1 = pb[1];
    float4 bp0 = ((const float4*)bp)[0];
    float4 bp1 = ((const float4*)bp)[1];
    float4 o0 = make_float4(a0.x + c0.x + bp0.x, a0.y + c0.y + bp0.y,
                            a0.z + c0.z + bp0.z, a0.w + c0.w + bp0.w);
    float4 o1 = make_float4(a1.x + c1.x + bp1.x, a1.y + c1.y + bp1.y,
                            a1.z + c1.z + bp1.z, a1.w + c1.w + bp1.w);
    ((float4*)out)[(size_t)e * 2 + 0] = o0;
    ((float4*)out)[(size_t)e * 2 + 1] = o1;
}

// ---------------- launch ----------------------------------------------------

extern "C" void kernel_launch(void* const* d_in, const int* in_sizes, int n_in,
                              void* d_out, int out_size) {
    const float* x    = (const float*)d_in[0];
    const int*   src  = (const int*)  d_in[1];
    const int*   dst  = (const int*)  d_in[2];
    const int*   psrc = (const int*)  d_in[3];
    const int*   pdst = (const int*)  d_in[4];
    const float* W1   = (const float*)d_in[5];
    const float* b1   = (const float*)d_in[6];
    const float* W2   = (const float*)d_in[7];
    const float* b2   = (const float*)d_in[8];
    const float* Wp   = (const float*)d_in[9];
    const float* bp   = (const float*)d_in[10];
    float* out = (float*)d_out;

    const int TB = 256;
    // degrees + per-edge dst-rank (arrays arrive zeroed: reset in k_edge_pred)
    k_degree<<<(N_EDGES + TB - 1) / TB, TB>>>(src, dst);

    // CSR build (by dst) + norms + fp16 layer-1 message conversion (fused)
    k_scan1<<<NB_SCAN, 256>>>();
    k_scan3_norms_scale<<<NB_SCAN, 256>>>(x);
    k_bucket<<<(N_EDGES + TB - 1) / TB, TB>>>(src, dst);   // atomic-free

    const int AGG_BLOCKS = N_NODES * 32 / TB;  // one warp per node, exact

    // layer 1
    k_aggregate<<<AGG_BLOCKS, TB>>>();
    k_node_update<0><<<1024, TB>>>(W1, b1);    // -> g_xh (fp16: relu * norm_out)

    // layer 2 (reads g_xh written by layer-1 update)
    k_aggregate<<<AGG_BLOCKS, TB>>>();
    k_node_update<1><<<1024, TB>>>(W2, b2);    // -> g_xh (fp16 h)

    // predictor (k_edge_pred also resets degree arrays for the next run)
    k_project<<<(N_NODES + 15) / 16, TB>>>(Wp);
    k_edge_pred<<<(N_PRED + TB - 1) / TB, TB>>>(psrc, pdst, bp, out);
}